// round 17
// baseline (speedup 1.0000x reference)
#include <cuda_runtime.h>
#include <cuda_bf16.h>
#include <math.h>
#include <stdint.h>

#define NMAX  100000
#define NMAX2 100096
#define C 128
#define C2 256
#define PP 64
#define DIST_TH 0.1f

// ---------------- scratch (device globals: allocation-free rule) --------------
__device__ int8_t g_fd1[(size_t)NMAX2 * C];
__device__ int8_t g_fd2[(size_t)NMAX2 * C];
__device__ float  g_fsc[4 * NMAX2];
__device__ int8_t g_hd1[(size_t)NMAX2 * C2];
__device__ int8_t g_hd2[(size_t)NMAX2 * C2];
__device__ float  g_hsc[8 * NMAX2];
__device__ int8_t g_gd1[(size_t)NMAX2 * C];
__device__ int8_t g_gd2[(size_t)NMAX2 * C];
__device__ float  g_gsc[4 * NMAX2];
__device__ float  g_h2[(size_t)NMAX2 * C];
__device__ float  g_a [(size_t)NMAX2 * C];
__device__ int8_t g_w1d1[C2 * C], g_w1d2[C2 * C];  __device__ float g_w1sc[C2];
__device__ int8_t g_w2d1[C * C2], g_w2d2[C * C2];  __device__ float g_w2sc[C];
__device__ int8_t g_wad1[C * C],  g_wad2[C * C];   __device__ float g_wasc[C];
__device__ int   g_idx[NMAX2];
__device__ unsigned long long g_maskArr[NMAX2];
__device__ int   g_cnt;
__device__ unsigned int g_maxU[C];
__device__ float g_num_on [PP * C];
__device__ float g_den_on [PP * C];
__device__ float g_num_off[PP * C];
__device__ float g_den_off[PP * C];

__device__ __forceinline__ unsigned int fkey(float f) {
    unsigned int u = __float_as_uint(f);
    return (u & 0x80000000u) ? ~u : (u | 0x80000000u);
}
__device__ __forceinline__ float funkey(unsigned int k) {
    unsigned int u = (k & 0x80000000u) ? (k & 0x7fffffffu) : ~k;
    return __uint_as_float(u);
}
__device__ __forceinline__ uint32_t smem_u32(const void* p) {
    uint32_t a;
    asm("{ .reg .u64 t; cvta.to.shared.u64 t, %1; cvt.u32.u64 %0, t; }" : "=r"(a) : "l"(p));
    return a;
}
#define CP16(dst, src, sz) \
    asm volatile("cp.async.cg.shared.global [%0], [%1], 16, %2;" \
                 :: "r"(dst), "l"(src), "r"(sz) : "memory")
#define CP_COMMIT() asm volatile("cp.async.commit_group;" ::: "memory")
#define CP_WAIT1() asm volatile("cp.async.wait_group 1;" ::: "memory")
#define CP_WAIT0() asm volatile("cp.async.wait_group 0;" ::: "memory")
#define LDSM4(r0, r1, r2, r3, addr) \
    asm volatile("ldmatrix.sync.aligned.m8n8.x4.shared.b16 {%0,%1,%2,%3}, [%4];" \
                 : "=r"(r0), "=r"(r1), "=r"(r2), "=r"(r3) : "r"(addr))
#define IMMA(S, A, B) \
    asm volatile("mma.sync.aligned.m16n8k32.row.col.s32.s8.s8.s32 " \
        "{%0,%1,%2,%3}, {%4,%5,%6,%7}, {%8,%9}, {%0,%1,%2,%3};" \
        : "+r"(S[0]), "+r"(S[1]), "+r"(S[2]), "+r"(S[3]) \
        : "r"(A[0]), "r"(A[1]), "r"(A[2]), "r"(A[3]), "r"(B[0]), "r"(B[1]))

// quantize 4 floats -> packed d1/d2 bytes
__device__ __forceinline__ void qpack4(float4 v, float invs, uint32_t& p1, uint32_t& p2) {
    float q[4] = {v.x * invs, v.y * invs, v.z * invs, v.w * invs};
    uint32_t a = 0, b = 0;
#pragma unroll
    for (int i = 0; i < 4; i++) {
        float r1 = rintf(q[i]);
        int d1 = (int)r1;
        int d2 = (int)rintf((q[i] - r1) * 256.f);
        d2 = d2 > 127 ? 127 : (d2 < -127 ? -127 : d2);
        a |= (uint32_t)(d1 & 255) << (8 * i);
        b |= (uint32_t)(d2 & 255) << (8 * i);
    }
    p1 = a; p2 = b;
}
__device__ __forceinline__ void qpair(float c0, float c1, float invs,
                                      unsigned short& p1, unsigned short& p2) {
    float q0 = c0 * invs, q1 = c1 * invs;
    float r0 = rintf(q0), r1 = rintf(q1);
    int e0 = (int)rintf((q0 - r0) * 256.f); e0 = e0 > 127 ? 127 : (e0 < -127 ? -127 : e0);
    int e1 = (int)rintf((q1 - r1) * 256.f); e1 = e1 > 127 ? 127 : (e1 < -127 ? -127 : e1);
    p1 = (unsigned short)(((int)r0 & 255) | (((int)r1 & 255) << 8));
    p2 = (unsigned short)((e0 & 255) | ((e1 & 255) << 8));
}

// ---------------- init: counters + pools + zero logits -----------------------
__global__ void init_kernel(float* out, int M) {
    int t = blockIdx.x * blockDim.x + threadIdx.x;
    int stride = gridDim.x * blockDim.x;
    if (t == 0) g_cnt = 0;
    if (t < C) g_maxU[t] = 0u;
    for (int i = t; i < PP * C; i += stride) {
        g_num_on[i] = 0.f; g_den_on[i] = 0.f;
        g_num_off[i] = 0.f; g_den_off[i] = 0.f;
    }
    for (int i = t; i < M; i += stride) out[i] = 0.f;
}

// ---------------- quantize feature: warp per row ------------------------------
__global__ void quant_feat(const float* __restrict__ src, int M) {
    int w = (blockIdx.x * blockDim.x + threadIdx.x) >> 5;
    int lane = threadIdx.x & 31;
    if (w >= M) return;
    float4 v = ((const float4*)(src + (size_t)w * C))[lane];
    float mx = fmaxf(fmaxf(fabsf(v.x), fabsf(v.y)), fmaxf(fabsf(v.z), fabsf(v.w)));
    mx = fmaxf(mx, __shfl_xor_sync(0xffffffffu, mx, 1));
    mx = fmaxf(mx, __shfl_xor_sync(0xffffffffu, mx, 2));
    mx = fmaxf(mx, __shfl_xor_sync(0xffffffffu, mx, 4));
    float invs = mx > 0.f ? 127.f / mx : 0.f;
    uint32_t p1, p2;
    qpack4(v, invs, p1, p2);
    ((uint32_t*)(g_fd1 + (size_t)w * C))[lane] = p1;
    ((uint32_t*)(g_fd2 + (size_t)w * C))[lane] = p2;
    if ((lane & 7) == 0) g_fsc[(lane >> 3) * NMAX2 + w] = mx * (1.f / 127.f);
}

// ---------------- quantize all weights: warp per output column ---------------
__global__ void quant_w_all(const float* __restrict__ W1,
                            const float* __restrict__ W2,
                            const float* __restrict__ Wa) {
    int w = (blockIdx.x * blockDim.x + threadIdx.x) >> 5;
    int lane = threadIdx.x & 31;
    const float* src; int8_t *d1, *d2; float* scv; int K, N, n;
    if (w < 256)      { src = W1; d1 = g_w1d1; d2 = g_w1d2; scv = g_w1sc; K = C;  N = C2; n = w; }
    else if (w < 384) { src = W2; d1 = g_w2d1; d2 = g_w2d2; scv = g_w2sc; K = C2; N = C;  n = w - 256; }
    else if (w < 512) { src = Wa; d1 = g_wad1; d2 = g_wad2; scv = g_wasc; K = C;  N = C;  n = w - 384; }
    else return;
    float buf[8];
    float mx = 0.f;
    int ng = K >> 7;                 // groups of 128 k
    for (int g = 0; g < ng; g++)
#pragma unroll
        for (int i = 0; i < 4; i++) {
            float x = src[(size_t)(g * 128 + lane * 4 + i) * N + n];
            buf[g * 4 + i] = x;
            mx = fmaxf(mx, fabsf(x));
        }
#pragma unroll
    for (int o = 16; o; o >>= 1) mx = fmaxf(mx, __shfl_xor_sync(0xffffffffu, mx, o));
    float invs = mx > 0.f ? 127.f / mx : 0.f;
    for (int g = 0; g < ng; g++) {
        float4 v = make_float4(buf[g * 4], buf[g * 4 + 1], buf[g * 4 + 2], buf[g * 4 + 3]);
        uint32_t p1, p2;
        qpack4(v, invs, p1, p2);
        *(uint32_t*)(d1 + (size_t)n * K + g * 128 + lane * 4) = p1;
        *(uint32_t*)(d2 + (size_t)n * K + g * 128 + lane * 4) = p2;
    }
    if (lane == 0) scv[n] = mx * (1.f / 127.f);
}

// ---------------- gather + quantize masked h2 rows ----------------------------
__global__ void gather_quant(const float* __restrict__ h2) {
    int cnt = g_cnt;
    int lane = threadIdx.x & 31;
    int w0 = (blockIdx.x * blockDim.x + threadIdx.x) >> 5;
    int nw = (gridDim.x * blockDim.x) >> 5;
    for (int i = w0; i < cnt; i += nw) {
        int n = g_idx[i];
        float4 v = ((const float4*)(h2 + (size_t)n * C))[lane];
        float mx = fmaxf(fmaxf(fabsf(v.x), fabsf(v.y)), fmaxf(fabsf(v.z), fabsf(v.w)));
        mx = fmaxf(mx, __shfl_xor_sync(0xffffffffu, mx, 1));
        mx = fmaxf(mx, __shfl_xor_sync(0xffffffffu, mx, 2));
        mx = fmaxf(mx, __shfl_xor_sync(0xffffffffu, mx, 4));
        float invs = mx > 0.f ? 127.f / mx : 0.f;
        uint32_t p1, p2;
        qpack4(v, invs, p1, p2);
        ((uint32_t*)(g_gd1 + (size_t)i * C))[lane] = p1;
        ((uint32_t*)(g_gd2 + (size_t)i * C))[lane] = p2;
        if ((lane & 7) == 0) g_gsc[(lane >> 3) * NMAX2 + i] = mx * (1.f / 127.f);
    }
}

// ---------------- int8 IMMA GEMM, 128x64 tile, 2-digit split ------------------
// K-chunk 32. Stage: A 128x64B(d1|d2) = 8KB, B 64x64B = 4KB, sA 512B = 12800B x3.
// Swizzle: physical 16B chunk = (2*digit + khalf) ^ ((row>>1)&3), 64B rows.
// MODE 0: FC1 (epi: relu(v*s+b) -> quantize -> h digit planes + scales)
// MODE 1: FC2 (epi: relu(v*s+b) -> h2 fp32 + logit partial atomicAdd)
// MODE 2: ATT (A = compacted h2 digits; epi: a fp32 + per-col max)
#define SOFF 12800
template<int MODE>
__global__ __launch_bounds__(256, 2)
void imma_gemm(const int8_t* __restrict__ Ad1, const int8_t* __restrict__ Ad2,
               const float* __restrict__ Asc,
               const int8_t* __restrict__ Bd1, const int8_t* __restrict__ Bd2,
               const float* __restrict__ Bscv,
               const float* __restrict__ scale, const float* __restrict__ bias,
               const float* __restrict__ W3, const float* __restrict__ b3,
               float* __restrict__ outLogit,
               int8_t* __restrict__ Od1, int8_t* __restrict__ Od2,
               float* __restrict__ Osc,
               float* __restrict__ Of,
               int M, int Ks, int Nn)
{
    extern __shared__ __align__(1024) char smx[];
    float* s_sc  = (float*)(smx + 3 * SOFF);
    float* s_bb  = s_sc + 64;
    float* s_w3  = s_bb + 64;
    float* s_red = s_w3 + 64;   // 128 floats (logit) or 64 max-keys

    const int tid = threadIdx.x;
    const int wid = tid >> 5, lane = tid & 31;
    const int warpm = wid & 3, warpn = wid >> 2;   // 4 x 2 warps: 32 rows x 32 cols
    const int gi = lane >> 2, ti = lane & 3;
    const int m0 = blockIdx.x * 128, n0 = blockIdx.y * 64;

    int Meff = M;
    if (MODE == 2) {
        Meff = g_cnt;
        if (m0 >= Meff) return;
    }

    if (tid < 64) {
        int col = n0 + tid;
        float sb = Bscv[col];
        s_sc[tid] = (MODE != 2) ? sb * scale[col] : sb;
        if (MODE != 2) s_bb[tid] = bias[col];
        if (MODE == 1) s_w3[tid] = W3[col];
    }
    if (MODE == 1 && tid < 128) s_red[tid] = 0.f;
    if (MODE == 2 && tid < 64) ((unsigned int*)s_red)[tid] = 0u;

    float acc[2][4][4];
#pragma unroll
    for (int a = 0; a < 2; a++)
#pragma unroll
        for (int b = 0; b < 4; b++)
#pragma unroll
            for (int c = 0; c < 4; c++) acc[a][b][c] = 0.f;

    const int nchunks = Ks >> 5;
    const uint32_t smu = smem_u32(smx);

    // cp.async geometry
    const int rA = tid >> 1, dA = tid & 1;
    const int grA = m0 + rA;
    const int okA = (grA < Meff) ? 16 : 0;
    const int8_t* pA = (dA ? Ad2 : Ad1) + (size_t)(okA ? grA : 0) * Ks;
    const uint32_t swA = (uint32_t)((rA >> 1) & 3);
    const uint32_t dstA0 = (uint32_t)rA * 64 + (((2u * dA + 0u) ^ swA) << 4);
    const uint32_t dstA1 = (uint32_t)rA * 64 + (((2u * dA + 1u) ^ swA) << 4);
    const int8_t* pB = (dA ? Bd2 : Bd1) + (size_t)(n0 + rA) * Ks;   // valid tid<128
    const uint32_t dstB0 = 8192u + (uint32_t)rA * 64 + (((2u * dA + 0u) ^ swA) << 4);
    const uint32_t dstB1 = 8192u + (uint32_t)rA * 64 + (((2u * dA + 1u) ^ swA) << 4);

    auto issue = [&](int ci) {
        uint32_t st = smu + (uint32_t)(ci % 3) * SOFF;
        int kc = ci << 5;
        CP16(st + dstA0, pA + kc, okA);
        CP16(st + dstA1, pA + kc + 16, okA);
        if (tid < 128) {
            CP16(st + dstB0, pB + kc, 16);
            CP16(st + dstB1, pB + kc + 16, 16);
        } else if (tid < 160) {
            int j = tid - 128;
            const char* s = (const char*)(Asc + (size_t)ci * NMAX2 + m0 + j * 4);
            CP16(st + 12288u + (uint32_t)j * 16, s, 16);
        }
        CP_COMMIT();
    };

    // ldmatrix per-lane offsets
    uint32_t offA[2][2], offB[2][2];
#pragma unroll
    for (int mt = 0; mt < 2; mt++) {
        int ra = warpm * 32 + mt * 16 + (lane & 15);
        uint32_t ha = (uint32_t)(lane >> 4);
        uint32_t sw = (uint32_t)((ra >> 1) & 3);
#pragma unroll
        for (int d = 0; d < 2; d++)
            offA[mt][d] = (uint32_t)ra * 64 + (((2u * d + ha) ^ sw) << 4);
    }
#pragma unroll
    for (int j = 0; j < 2; j++) {
        int rb = warpn * 32 + j * 16 + ((lane >> 4) << 3) + (lane & 7);
        uint32_t hb = (uint32_t)((lane >> 3) & 1);
        uint32_t sw = (uint32_t)((rb >> 1) & 3);
#pragma unroll
        for (int d = 0; d < 2; d++)
            offB[j][d] = 8192u + (uint32_t)rb * 64 + (((2u * d + hb) ^ sw) << 4);
    }

    issue(0);
    if (nchunks > 1) issue(1);

    for (int ci = 0; ci < nchunks; ci++) {
        if (ci + 1 < nchunks) { CP_WAIT1(); } else { CP_WAIT0(); }
        __syncthreads();
        if (ci + 2 < nchunks) issue(ci + 2);

        uint32_t base = smu + (uint32_t)(ci % 3) * SOFF;
        uint32_t aH[2][4], aM[2][4], bH[4][2], bM[4][2];
#pragma unroll
        for (int mt = 0; mt < 2; mt++) {
            LDSM4(aH[mt][0], aH[mt][1], aH[mt][2], aH[mt][3], base + offA[mt][0]);
            LDSM4(aM[mt][0], aM[mt][1], aM[mt][2], aM[mt][3], base + offA[mt][1]);
        }
#pragma unroll
        for (int j = 0; j < 2; j++) {
            LDSM4(bH[2 * j][0], bH[2 * j][1], bH[2 * j + 1][0], bH[2 * j + 1][1],
                  base + offB[j][0]);
            LDSM4(bM[2 * j][0], bM[2 * j][1], bM[2 * j + 1][0], bM[2 * j + 1][1],
                  base + offB[j][1]);
        }
        float sAv[2][2];
        const float* sabuf = (const float*)(smx + (size_t)(ci % 3) * SOFF + 12288);
#pragma unroll
        for (int mt = 0; mt < 2; mt++)
#pragma unroll
            for (int h = 0; h < 2; h++)
                sAv[mt][h] = sabuf[warpm * 32 + mt * 16 + gi + h * 8];

        int S[2][4][4];
        // phase 1: d1*d1
#pragma unroll
        for (int mt = 0; mt < 2; mt++)
#pragma unroll
            for (int nt = 0; nt < 4; nt++) {
#pragma unroll
                for (int q = 0; q < 4; q++) S[mt][nt][q] = 0;
                IMMA(S[mt][nt], aH[mt], bH[nt]);
            }
#pragma unroll
        for (int mt = 0; mt < 2; mt++)
#pragma unroll
            for (int nt = 0; nt < 4; nt++)
#pragma unroll
                for (int h = 0; h < 2; h++)
#pragma unroll
                    for (int e = 0; e < 2; e++)
                        acc[mt][nt][2 * h + e] =
                            fmaf(sAv[mt][h], __int2float_rn(S[mt][nt][2 * h + e]),
                                 acc[mt][nt][2 * h + e]);
        // phase 2: d1*d2 + d2*d1, weight /256
#pragma unroll
        for (int mt = 0; mt < 2; mt++)
#pragma unroll
            for (int nt = 0; nt < 4; nt++) {
#pragma unroll
                for (int q = 0; q < 4; q++) S[mt][nt][q] = 0;
                IMMA(S[mt][nt], aH[mt], bM[nt]);
                IMMA(S[mt][nt], aM[mt], bH[nt]);
            }
#pragma unroll
        for (int mt = 0; mt < 2; mt++)
#pragma unroll
            for (int nt = 0; nt < 4; nt++)
#pragma unroll
                for (int h = 0; h < 2; h++)
#pragma unroll
                    for (int e = 0; e < 2; e++)
                        acc[mt][nt][2 * h + e] =
                            fmaf(sAv[mt][h] * (1.f / 256.f),
                                 __int2float_rn(S[mt][nt][2 * h + e]),
                                 acc[mt][nt][2 * h + e]);
        __syncthreads();
    }

    // ---------------- epilogue ----------------
    float cmax[4][2];
    if (MODE == 2) {
#pragma unroll
        for (int nt = 0; nt < 4; nt++) { cmax[nt][0] = -INFINITY; cmax[nt][1] = -INFINITY; }
    }
    float lsum[2][2] = {{0.f, 0.f}, {0.f, 0.f}};

#pragma unroll
    for (int mt = 0; mt < 2; mt++) {
#pragma unroll
        for (int hf = 0; hf < 2; hf++) {
            int rowL = warpm * 32 + mt * 16 + gi + hf * 8;
            int row = m0 + rowL;
            bool vrow = row < Meff;
            float v[4][2];
            float rmax = 0.f;
#pragma unroll
            for (int nt = 0; nt < 4; nt++)
#pragma unroll
                for (int e = 0; e < 2; e++) {
                    int colL = warpn * 32 + nt * 8 + 2 * ti + e;
                    float cc = acc[mt][nt][2 * hf + e] * s_sc[colL];
                    if (MODE != 2) cc = fmaxf(cc + s_bb[colL], 0.f);
                    v[nt][e] = cc;
                    if (MODE == 0) rmax = fmaxf(rmax, fabsf(cc));
                }
            if (MODE == 0) {
                rmax = fmaxf(rmax, __shfl_xor_sync(0xffffffffu, rmax, 1));
                rmax = fmaxf(rmax, __shfl_xor_sync(0xffffffffu, rmax, 2));
                float invs = rmax > 0.f ? 127.f / rmax : 0.f;
                if (vrow) {
#pragma unroll
                    for (int nt = 0; nt < 4; nt++) {
                        unsigned short p1, p2;
                        qpair(v[nt][0], v[nt][1], invs, p1, p2);
                        size_t off = (size_t)row * Nn + n0 + warpn * 32 + nt * 8 + 2 * ti;
                        *(unsigned short*)(Od1 + off) = p1;
                        *(unsigned short*)(Od2 + off) = p2;
                    }
                    if (ti == 0)
                        Osc[(size_t)((n0 + warpn * 32) >> 5) * NMAX2 + row] =
                            rmax * (1.f / 127.f);
                }
            } else if (MODE == 1) {
                if (vrow) {
#pragma unroll
                    for (int nt = 0; nt < 4; nt++)
                        *(float2*)(Of + (size_t)row * C + n0 + warpn * 32 + nt * 8 + 2 * ti) =
                            make_float2(v[nt][0], v[nt][1]);
                }
                float p = 0.f;
#pragma unroll
                for (int nt = 0; nt < 4; nt++) {
                    int colL = warpn * 32 + nt * 8 + 2 * ti;
                    p = fmaf(v[nt][0], s_w3[colL], p);
                    p = fmaf(v[nt][1], s_w3[colL + 1], p);
                }
                lsum[mt][hf] = p;
            } else {
                if (vrow) {
#pragma unroll
                    for (int nt = 0; nt < 4; nt++) {
                        *(float2*)(Of + (size_t)row * C + n0 + warpn * 32 + nt * 8 + 2 * ti) =
                            make_float2(v[nt][0], v[nt][1]);
                        cmax[nt][0] = fmaxf(cmax[nt][0], v[nt][0]);
                        cmax[nt][1] = fmaxf(cmax[nt][1], v[nt][1]);
                    }
                }
            }
        }
    }

    if (MODE == 1) {
#pragma unroll
        for (int mt = 0; mt < 2; mt++)
#pragma unroll
            for (int hf = 0; hf < 2; hf++)
                atomicAdd(&s_red[warpm * 32 + mt * 16 + gi + hf * 8], lsum[mt][hf]);
        __syncthreads();
        if (tid < 128) {
            int row = m0 + tid;
            if (row < Meff)
                atomicAdd(outLogit + row, s_red[tid] + (n0 == 0 ? b3[0] : 0.f));
        }
    } else if (MODE == 2) {
        unsigned int* sr = (unsigned int*)s_red;
#pragma unroll
        for (int nt = 0; nt < 4; nt++)
#pragma unroll
            for (int e = 0; e < 2; e++) {
                if (cmax[nt][e] > -INFINITY)
                    atomicMax(&sr[warpn * 32 + nt * 8 + 2 * ti + e], fkey(cmax[nt][e]));
            }
        __syncthreads();
        if (tid < 64 && ((unsigned int*)s_red)[tid] != 0u)
            atomicMax(&g_maxU[n0 + tid], ((unsigned int*)s_red)[tid]);
    }
}

// ---------------- mask pass: compact hit points ------------------------------
__global__ void mask_kernel(const float* __restrict__ xyz,
                            const float* __restrict__ pc,
                            const float* __restrict__ pn,
                            const float* __restrict__ pmn,
                            const float* __restrict__ pmx, int M)
{
    __shared__ float s_n0[PP], s_n1[PP], s_n2[PP], s_off[PP];
    __shared__ float s_mn0[PP], s_mn1[PP], s_mx0[PP], s_mx1[PP];
    int t = threadIdx.x;
    if (t < PP) {
        float a0 = pn[t * 3], a1 = pn[t * 3 + 1], a2 = pn[t * 3 + 2];
        s_n0[t] = a0; s_n1[t] = a1; s_n2[t] = a2;
        s_off[t] = pc[t * 3] * a0 + pc[t * 3 + 1] * a1 + pc[t * 3 + 2] * a2;
        s_mn0[t] = pmn[t * 3]; s_mn1[t] = pmn[t * 3 + 1];
        s_mx0[t] = pmx[t * 3]; s_mx1[t] = pmx[t * 3 + 1];
    }
    __syncthreads();
    int n = blockIdx.x * blockDim.x + t;
    if (n >= M) return;
    float x = xyz[n * 3], y = xyz[n * 3 + 1], z = xyz[n * 3 + 2];
    unsigned long long mask = 0ull;
#pragma unroll
    for (int p = 0; p < PP; p++) {
        float proj = x * s_n0[p] + y * s_n1[p] + z * s_n2[p];
        bool hit = (fabsf(proj - s_off[p]) < DIST_TH) &&
                   (x >= s_mn0[p]) && (x < s_mx0[p]) &&
                   (y >= s_mn1[p]) && (y < s_mx1[p]);
        if (hit) mask |= (1ull << p);
    }
    if (mask) {
        int pos = atomicAdd(&g_cnt, 1);
        g_idx[pos] = n;
        g_maskArr[pos] = mask;
    }
}

// ---------------- pooling scatter over compacted points ----------------------
__global__ void pool2_kernel(const float* __restrict__ logit)
{
    __shared__ float s_amax[C];
    if (threadIdx.x < C) s_amax[threadIdx.x] = funkey(g_maxU[threadIdx.x]);
    __syncthreads();
    int cnt = g_cnt;
    int stride = gridDim.x * blockDim.x;
    for (int i = blockIdx.x * blockDim.x + threadIdx.x; i < cnt; i += stride) {
        int n = g_idx[i];
        unsigned long long mask = g_maskArr[i];
        bool on = logit[n] > 0.0f;
        float* numB = on ? g_num_on : g_num_off;
        float* denB = on ? g_den_on : g_den_off;
        const float* ar = g_a + (size_t)i * C;
        const float* hr = g_h2 + (size_t)n * C;
        for (int c = 0; c < C; c += 4) {
            float4 a4 = *(const float4*)(ar + c);
            float4 h4 = *(const float4*)(hr + c);
            float e0 = expf(a4.x - s_amax[c + 0]);
            float e1 = expf(a4.y - s_amax[c + 1]);
            float e2 = expf(a4.z - s_amax[c + 2]);
            float e3 = expf(a4.w - s_amax[c + 3]);
            unsigned long long mm = mask;
            while (mm) {
                int p = __ffsll(mm) - 1;
                mm &= mm - 1;
                float* dn = denB + p * C + c;
                float* nm = numB + p * C + c;
                atomicAdd(dn + 0, e0); atomicAdd(dn + 1, e1);
                atomicAdd(dn + 2, e2); atomicAdd(dn + 3, e3);
                atomicAdd(nm + 0, e0 * h4.x); atomicAdd(nm + 1, e1 * h4.y);
                atomicAdd(nm + 2, e2 * h4.z); atomicAdd(nm + 3, e3 * h4.w);
            }
        }
    }
}

// ---------------- finalize: agg -> relu(agg@Wm+bm), concat ori --------------
__global__ void finalize_kernel(const float* __restrict__ Wm,
                                const float* __restrict__ bm,
                                const float* __restrict__ pc,
                                const float* __restrict__ pn,
                                const float* __restrict__ pmn,
                                const float* __restrict__ pmx,
                                float* __restrict__ out, int M)
{
    int p = blockIdx.x;
    int c = threadIdx.x;
    __shared__ float aggOn[C], aggOff[C];
    aggOn[c]  = g_num_on [p * C + c] / (g_den_on [p * C + c] + 1e-9f);
    aggOff[c] = g_num_off[p * C + c] / (g_den_off[p * C + c] + 1e-9f);
    __syncthreads();
    float so = 0.f, sf = 0.f;
#pragma unroll 8
    for (int k = 0; k < C; k++) {
        float w = Wm[k * C + c];
        so = fmaf(aggOn[k], w, so);
        sf = fmaf(aggOff[k], w, sf);
    }
    float bb = bm[c];
    float* onRow  = out + M + (size_t)p * (C + 12);
    float* offRow = out + M + (size_t)PP * (C + 12) + (size_t)p * (C + 12);
    onRow[c]  = fmaxf(so + bb, 0.f);
    offRow[c] = fmaxf(sf + bb, 0.f);
    if (c < 12) {
        int axis = c % 3, grp = c / 3;
        const float* src = (grp == 0) ? pc : (grp == 1) ? pn : (grp == 2) ? pmn : pmx;
        float v = src[p * 3 + axis];
        onRow[C + c] = v;
        offRow[C + c] = v;
    }
}

// ---------------- launch ----------------
extern "C" void kernel_launch(void* const* d_in, const int* in_sizes, int n_in,
                              void* d_out, int out_size)
{
    const float* feature = (const float*)d_in[0];
    const float* xyz     = (const float*)d_in[1];
    const float* pc      = (const float*)d_in[2];
    const float* pn      = (const float*)d_in[3];
    const float* pmn     = (const float*)d_in[4];
    const float* pmx     = (const float*)d_in[5];
    const float* W1      = (const float*)d_in[6];
    const float* s1      = (const float*)d_in[7];
    const float* b1      = (const float*)d_in[8];
    const float* W2      = (const float*)d_in[9];
    const float* s2      = (const float*)d_in[10];
    const float* b2      = (const float*)d_in[11];
    const float* W3      = (const float*)d_in[12];
    const float* b3      = (const float*)d_in[13];
    const float* Wa      = (const float*)d_in[14];
    const float* Wm      = (const float*)d_in[15];
    const float* bm      = (const float*)d_in[16];

    int M = in_sizes[1] / 3;            // N = 100000
    float* out = (float*)d_out;

    int8_t *fd1, *fd2, *hd1, *hd2, *gd1, *gd2;
    int8_t *w1d1, *w1d2, *w2d1, *w2d2, *wad1, *wad2;
    float *fsc, *hsc, *gsc, *w1sc, *w2sc, *wasc, *h2P, *aP;
    cudaGetSymbolAddress((void**)&fd1, g_fd1);
    cudaGetSymbolAddress((void**)&fd2, g_fd2);
    cudaGetSymbolAddress((void**)&fsc, g_fsc);
    cudaGetSymbolAddress((void**)&hd1, g_hd1);
    cudaGetSymbolAddress((void**)&hd2, g_hd2);
    cudaGetSymbolAddress((void**)&hsc, g_hsc);
    cudaGetSymbolAddress((void**)&gd1, g_gd1);
    cudaGetSymbolAddress((void**)&gd2, g_gd2);
    cudaGetSymbolAddress((void**)&gsc, g_gsc);
    cudaGetSymbolAddress((void**)&w1d1, g_w1d1);
    cudaGetSymbolAddress((void**)&w1d2, g_w1d2);
    cudaGetSymbolAddress((void**)&w1sc, g_w1sc);
    cudaGetSymbolAddress((void**)&w2d1, g_w2d1);
    cudaGetSymbolAddress((void**)&w2d2, g_w2d2);
    cudaGetSymbolAddress((void**)&w2sc, g_w2sc);
    cudaGetSymbolAddress((void**)&wad1, g_wad1);
    cudaGetSymbolAddress((void**)&wad2, g_wad2);
    cudaGetSymbolAddress((void**)&wasc, g_wasc);
    cudaGetSymbolAddress((void**)&h2P, g_h2);
    cudaGetSymbolAddress((void**)&aP,  g_a);

    const int SMEM = 3 * SOFF + 2048;      // 40448
    cudaFuncSetAttribute(imma_gemm<0>, cudaFuncAttributeMaxDynamicSharedMemorySize, SMEM);
    cudaFuncSetAttribute(imma_gemm<1>, cudaFuncAttributeMaxDynamicSharedMemorySize, SMEM);
    cudaFuncSetAttribute(imma_gemm<2>, cudaFuncAttributeMaxDynamicSharedMemorySize, SMEM);

    int gx = (M + 127) / 128;              // 782

    init_kernel<<<512, 256>>>(out, M);
    mask_kernel<<<(M + 255) / 256, 256>>>(xyz, pc, pn, pmn, pmx, M);
    quant_feat<<<(M * 32 + 255) / 256, 256>>>(feature, M);
    quant_w_all<<<64, 256>>>(W1, W2, Wa);

    // FC1: h = relu((feature@W1)*s1+b1) -> quantized h planes   [M,128]x[128,256]
    imma_gemm<0><<<dim3(gx, 4), 256, SMEM>>>(fd1, fd2, fsc, w1d1, w1d2, w1sc,
                                             s1, b1, nullptr, nullptr, nullptr,
                                             hd1, hd2, hsc, nullptr, M, C, C2);
    // FC2: h2 = relu((h@W2)*s2+b2) fp32 + logit (atomic partials) -> out[0..M)
    imma_gemm<1><<<dim3(gx, 2), 256, SMEM>>>(hd1, hd2, hsc, w2d1, w2d2, w2sc,
                                             s2, b2, W3, b3, out,
                                             nullptr, nullptr, nullptr, h2P, M, C2, C);
    // gather + quantize masked h2 rows
    gather_quant<<<128, 256>>>(h2P);
    // ATT: a = h2_masked @ Wa + per-channel max
    imma_gemm<2><<<dim3(gx, 2), 256, SMEM>>>(gd1, gd2, gsc, wad1, wad2, wasc,
                                             nullptr, nullptr, nullptr, nullptr, nullptr,
                                             nullptr, nullptr, nullptr, aP, M, C, C);
    // sparse masked softmax pooling scatter
    pool2_kernel<<<256, 256>>>(out);
    // tiny per-plane GEMM + ori concat
    finalize_kernel<<<PP, 128>>>(Wm, bm, pc, pn, pmn, pmx, out, M);
}